// round 2
// baseline (speedup 1.0000x reference)
#include <cuda_runtime.h>
#include <cuda_bf16.h>

#define NN   100000
#define EE   1600000
#define EOUT 400000
#define HIDD 64
#define STATS_BLOCKS 512
#define BN_EPS 1e-5f

// ---------------- scratch (device globals; no allocation) ----------------
__device__ float g_dinv[NN];
__device__ int   g_deg[NN];
__device__ float g_x  [NN * HIDD];   // x_embed
__device__ float g_hw [NN * HIDD];   // x_embed @ W_l
__device__ float g_agg[NN * HIDD];   // aggregated messages
__device__ float g_part[STATS_BLOCKS * 128]; // per-block partial sum/sumsq
__device__ float g_scale[HIDD];
__device__ float g_shift[HIDD];

// ---------------- degree ----------------
__global__ void k_deg_init() {
    int i = blockIdx.x * 256 + threadIdx.x;
    if (i < NN) g_deg[i] = 1;            // self loop
}

__global__ void k_deg_count(const int* __restrict__ ei) {
    int e = blockIdx.x * 256 + threadIdx.x;
    if (e < EE) {
        int d = ei[EE + e];              // row 1 = dst
        atomicAdd(&g_deg[d], 1);
    }
}

__global__ void k_dinv() {
    int i = blockIdx.x * 256 + threadIdx.x;
    if (i < NN) g_dinv[i] = rsqrtf((float)g_deg[i]);
}

// ---------------- node embedding: x[N,16] @ W_emb[16,64] + b ----------------
__global__ void k_embed(const float* __restrict__ x,
                        const float* __restrict__ W,
                        const float* __restrict__ b) {
    __shared__ float Ws[16 * 64];
    int t = threadIdx.x;                 // 256
    #pragma unroll
    for (int i = t; i < 16 * 64; i += 256) Ws[i] = W[i];
    __syncthreads();
    int id = blockIdx.x * 256 + t;
    int n = id >> 6, h = id & 63;
    if (n >= NN) return;
    float acc = b[h];
    #pragma unroll
    for (int k = 0; k < 16; k++)
        acc = fmaf(x[n * 16 + k], Ws[k * 64 + h], acc);
    g_x[n * 64 + h] = acc;
}

// ---------------- per-layer GEMM + agg init (self-loop + bias fused) --------
__global__ void k_gemm_agg(const float* __restrict__ W,   // [64,64] row-major (in,out)
                           const float* __restrict__ b) { // [64]
    __shared__ float Ws[64 * 64];
    __shared__ float xs[4][64];
    int t = threadIdx.x;                 // 256
    for (int i = t; i < 64 * 64; i += 256) Ws[i] = W[i];
    int ni = t >> 6, h = t & 63;
    int n = blockIdx.x * 4 + ni;
    if (n < NN) xs[ni][h] = g_x[n * 64 + h];
    __syncthreads();
    if (n >= NN) return;
    float acc = 0.f;
    #pragma unroll
    for (int k = 0; k < 64; k++)
        acc = fmaf(xs[ni][k], Ws[k * 64 + h], acc);
    g_hw[n * 64 + h] = acc;
    float di = g_dinv[n];
    g_agg[n * 64 + h] = fmaf(acc, di * di, b[h]);   // self-loop + conv bias
}

// ---------------- edge scatter (16 threads / edge, float4 gather) ----------
__global__ void k_scatter(const int* __restrict__ ei) {
    int tid = blockIdx.x * 256 + threadIdx.x;
    int e = tid >> 4;
    if (e >= EE) return;
    int c = tid & 15;
    int s = ei[e];
    int d = ei[EE + e];
    float nrm = g_dinv[s] * g_dinv[d];
    float4 v = reinterpret_cast<const float4*>(g_hw)[s * 16 + c];
    float* a = &g_agg[d * 64 + c * 4];
    atomicAdd(a + 0, v.x * nrm);
    atomicAdd(a + 1, v.y * nrm);
    atomicAdd(a + 2, v.z * nrm);
    atomicAdd(a + 3, v.w * nrm);
}

// ---------------- BN stats: per-feature sum & sumsq partials ----------------
__global__ void k_stats() {
    __shared__ float ss[256], sq[256];
    int t = threadIdx.x;                 // 256
    int f = t & 63, g = t >> 6;          // 4 node-groups per block
    float s = 0.f, q = 0.f;
    for (int n = blockIdx.x * 4 + g; n < NN; n += STATS_BLOCKS * 4) {
        float v = g_agg[n * 64 + f];
        s += v; q = fmaf(v, v, q);
    }
    ss[t] = s; sq[t] = q;
    __syncthreads();
    if (g == 0) {
        s = ss[f] + ss[64 + f] + ss[128 + f] + ss[192 + f];
        q = sq[f] + sq[64 + f] + sq[128 + f] + sq[192 + f];
        g_part[blockIdx.x * 128 + f]      = s;
        g_part[blockIdx.x * 128 + 64 + f] = q;
    }
}

// ---------------- BN finalize: scale/shift ----------------
__global__ void k_bnfin(const float* __restrict__ gamma,
                        const float* __restrict__ beta) {
    __shared__ float sh[128];
    int t = threadIdx.x;                 // 128
    float s = 0.f;
    for (int i = 0; i < STATS_BLOCKS; i++) s += g_part[i * 128 + t];
    sh[t] = s;
    __syncthreads();
    if (t < 64) {
        float mean = sh[t] * (1.0f / NN);
        float var  = sh[64 + t] * (1.0f / NN) - mean * mean;
        float sc   = gamma[t] * rsqrtf(var + BN_EPS);
        g_scale[t] = sc;
        g_shift[t] = beta[t] - mean * sc;
    }
}

// ---------------- BN apply + ReLU + residual ----------------
__global__ void k_apply() {
    int id = blockIdx.x * 256 + threadIdx.x;   // over N*16 float4s
    if (id >= NN * 16) return;
    int c = id & 15;
    float4 a = reinterpret_cast<const float4*>(g_agg)[id];
    float4 sc = reinterpret_cast<const float4*>(g_scale)[c];
    float4 sf = reinterpret_cast<const float4*>(g_shift)[c];
    float4 xv = reinterpret_cast<const float4*>(g_x)[id];
    xv.x += fmaxf(fmaf(a.x, sc.x, sf.x), 0.f);
    xv.y += fmaxf(fmaf(a.y, sc.y, sf.y), 0.f);
    xv.z += fmaxf(fmaf(a.z, sc.z, sf.z), 0.f);
    xv.w += fmaxf(fmaf(a.w, sc.w, sf.w), 0.f);
    reinterpret_cast<float4*>(g_x)[id] = xv;
}

// ---------------- edge head: [x[src] ; x[dst]] @ fc_W + fc_b ----------------
__global__ void k_final(const int* __restrict__ eio,
                        const float* __restrict__ fcW,   // [128,2]
                        const float* __restrict__ fcb,   // [2]
                        float* __restrict__ out) {
    int wid = (blockIdx.x * 256 + threadIdx.x) >> 5;
    int lane = threadIdx.x & 31;
    if (wid >= EOUT) return;
    int es = eio[wid];
    int ed = eio[EOUT + wid];
    float a0 = 0.f, a1 = 0.f, v;
    v = g_x[es * 64 + lane];
    a0 = fmaf(v, fcW[lane * 2],            a0); a1 = fmaf(v, fcW[lane * 2 + 1],        a1);
    v = g_x[es * 64 + 32 + lane];
    a0 = fmaf(v, fcW[(32 + lane) * 2],     a0); a1 = fmaf(v, fcW[(32 + lane) * 2 + 1], a1);
    v = g_x[ed * 64 + lane];
    a0 = fmaf(v, fcW[(64 + lane) * 2],     a0); a1 = fmaf(v, fcW[(64 + lane) * 2 + 1], a1);
    v = g_x[ed * 64 + 32 + lane];
    a0 = fmaf(v, fcW[(96 + lane) * 2],     a0); a1 = fmaf(v, fcW[(96 + lane) * 2 + 1], a1);
    #pragma unroll
    for (int o = 16; o; o >>= 1) {
        a0 += __shfl_down_sync(0xffffffffu, a0, o);
        a1 += __shfl_down_sync(0xffffffffu, a1, o);
    }
    if (lane == 0) {
        out[wid * 2 + 0] = a0 + fcb[0];
        out[wid * 2 + 1] = a1 + fcb[1];
    }
}

// ---------------- launch ----------------
extern "C" void kernel_launch(void* const* d_in, const int* in_sizes, int n_in,
                              void* d_out, int out_size) {
    const float* x    = (const float*)d_in[0];
    const int*   ei   = (const int*)d_in[1];    // [2, E] int32 (JAX x64 disabled)
    const int*   eio  = (const int*)d_in[2];    // [2, E_out] int32
    const float* Wemb = (const float*)d_in[3];
    const float* bemb = (const float*)d_in[4];
    const float* convW= (const float*)d_in[5];  // [6,64,64]
    const float* convb= (const float*)d_in[6];  // [6,64]
    const float* gam  = (const float*)d_in[7];  // [6,64]
    const float* bet  = (const float*)d_in[8];  // [6,64]
    const float* fcW  = (const float*)d_in[9];  // [128,2]
    const float* fcb  = (const float*)d_in[10]; // [2]
    float*       out  = (float*)d_out;

    k_deg_init<<<(NN + 255) / 256, 256>>>();
    k_deg_count<<<(EE + 255) / 256, 256>>>(ei);
    k_dinv<<<(NN + 255) / 256, 256>>>();
    k_embed<<<(NN * 64 + 255) / 256, 256>>>(x, Wemb, bemb);

    for (int l = 0; l < 6; l++) {
        k_gemm_agg<<<(NN + 3) / 4, 256>>>(convW + l * 64 * 64, convb + l * 64);
        k_scatter<<<(EE * 16 + 255) / 256, 256>>>(ei);
        k_stats<<<STATS_BLOCKS, 256>>>();
        k_bnfin<<<1, 128>>>(gam + l * 64, bet + l * 64);
        k_apply<<<(NN * 16 + 255) / 256, 256>>>();
    }

    k_final<<<(EOUT * 32 + 255) / 256, 256>>>(eio, fcW, fcb, out);
}

// round 3
// speedup vs baseline: 2.3765x; 2.3765x over previous
#include <cuda_runtime.h>
#include <cuda_bf16.h>

#define NN   100000
#define EE   1600000
#define EOUT 400000
#define HIDD 64
#define STATS_BLOCKS 512
#define BN_EPS 1e-5f

// ---------------- scratch (device globals; no allocation) ----------------
__device__ float g_dinv[NN];
__device__ int   g_deg[NN];
__device__ int   g_rowptr[NN + 1];
__device__ int   g_cursor[NN];
__device__ int2  g_csr[EE];          // (src, norm-bits)
__device__ float g_x  [NN * HIDD];   // x_embed
__device__ float g_hw [NN * HIDD];   // aggregated x (pre-GEMM)
__device__ float g_agg[NN * HIDD];   // conv output
__device__ float g_part[STATS_BLOCKS * 128];
__device__ float g_scale[HIDD];
__device__ float g_shift[HIDD];

// ---------------- degree ----------------
__global__ void k_deg_init() {
    int i = blockIdx.x * 256 + threadIdx.x;
    if (i < NN) g_deg[i] = 1;            // self loop
}

__global__ void k_deg_count(const int* __restrict__ ei) {
    int e = blockIdx.x * 256 + threadIdx.x;
    if (e < EE) atomicAdd(&g_deg[ei[EE + e]], 1);
}

__global__ void k_dinv() {
    int i = blockIdx.x * 256 + threadIdx.x;
    if (i < NN) g_dinv[i] = rsqrtf((float)g_deg[i]);
}

// ---------------- exclusive scan of (deg-1) -> rowptr/cursor (1 block) -----
__global__ void k_scan() {
    __shared__ int wsum[32];
    __shared__ int run_s;
    int tid = threadIdx.x;               // 1024
    int lane = tid & 31, wid = tid >> 5;
    if (tid == 0) run_s = 0;
    __syncthreads();
    for (int base = 0; base < NN; base += 1024) {
        int i = base + tid;
        int v = (i < NN) ? g_deg[i] - 1 : 0;
        int incl = v;
        #pragma unroll
        for (int o = 1; o < 32; o <<= 1) {
            int t = __shfl_up_sync(0xffffffffu, incl, o);
            if (lane >= o) incl += t;
        }
        if (lane == 31) wsum[wid] = incl;
        __syncthreads();
        if (wid == 0) {
            int s = wsum[lane];
            #pragma unroll
            for (int o = 1; o < 32; o <<= 1) {
                int t = __shfl_up_sync(0xffffffffu, s, o);
                if (lane >= o) s += t;
            }
            wsum[lane] = s;
        }
        __syncthreads();
        int wex = wid ? wsum[wid - 1] : 0;
        int total = wsum[31];
        int excl = run_s + wex + incl - v;
        if (i < NN) { g_rowptr[i] = excl; g_cursor[i] = excl; }
        __syncthreads();
        if (tid == 0) run_s += total;
        __syncthreads();
    }
    if (threadIdx.x == 0) g_rowptr[NN] = run_s;
}

// ---------------- CSR fill ----------------
__global__ void k_fill(const int* __restrict__ ei) {
    int e = blockIdx.x * 256 + threadIdx.x;
    if (e >= EE) return;
    int s = ei[e], d = ei[EE + e];
    int p = atomicAdd(&g_cursor[d], 1);
    g_csr[p] = make_int2(s, __float_as_int(g_dinv[s] * g_dinv[d]));
}

// ---------------- node embedding: x[N,16] @ W_emb[16,64] + b ----------------
__global__ void k_embed(const float* __restrict__ x,
                        const float* __restrict__ W,
                        const float* __restrict__ b) {
    __shared__ float Ws[16 * 64];
    int t = threadIdx.x;                 // 256
    #pragma unroll
    for (int i = t; i < 16 * 64; i += 256) Ws[i] = W[i];
    __syncthreads();
    int id = blockIdx.x * 256 + t;
    int n = id >> 6, h = id & 63;
    if (n >= NN) return;
    float acc = b[h];
    #pragma unroll
    for (int k = 0; k < 16; k++)
        acc = fmaf(x[n * 16 + k], Ws[k * 64 + h], acc);
    g_x[n * 64 + h] = acc;
}

// ---------------- gather: hw[n] = sum nrm*x[src] + dinv^2*x[n] --------------
__global__ void k_gather() {
    int t = blockIdx.x * 256 + threadIdx.x;
    int node = t >> 5;
    if (node >= NN) return;
    int lane = t & 31;
    const float2* x2 = (const float2*)g_x;
    int beg = g_rowptr[node], end = g_rowptr[node + 1];
    float di = g_dinv[node];
    float2 acc = x2[node * 32 + lane];
    acc.x *= di * di; acc.y *= di * di;
    float2 acc2 = make_float2(0.f, 0.f);
    int i = beg;
    for (; i + 1 < end; i += 2) {
        int2 a = g_csr[i];
        int2 c = g_csr[i + 1];
        float2 va = x2[a.x * 32 + lane];
        float2 vb = x2[c.x * 32 + lane];
        float na = __int_as_float(a.y), nb = __int_as_float(c.y);
        acc.x  = fmaf(na, va.x, acc.x);  acc.y  = fmaf(na, va.y, acc.y);
        acc2.x = fmaf(nb, vb.x, acc2.x); acc2.y = fmaf(nb, vb.y, acc2.y);
    }
    if (i < end) {
        int2 a = g_csr[i];
        float2 va = x2[a.x * 32 + lane];
        float na = __int_as_float(a.y);
        acc.x = fmaf(na, va.x, acc.x); acc.y = fmaf(na, va.y, acc.y);
    }
    acc.x += acc2.x; acc.y += acc2.y;
    ((float2*)g_hw)[node * 32 + lane] = acc;
}

// ---------------- GEMM: agg = hw @ W + b (node per thread) ------------------
__global__ void __launch_bounds__(256) k_gemm(const float* __restrict__ W,
                                              const float* __restrict__ b) {
    __shared__ float Ws[64 * 64];
    __shared__ float bs[64];
    int tid = threadIdx.x;               // 256
    for (int i = tid; i < 64 * 64; i += 256) Ws[i] = W[i];
    if (tid < 64) bs[tid] = b[tid];
    __syncthreads();
    int n = blockIdx.x * 256 + tid;
    if (n >= NN) return;
    float acc[64];
    #pragma unroll
    for (int h = 0; h < 64; h++) acc[h] = 0.f;
    const float4* x4 = (const float4*)(g_hw + (size_t)n * 64);
    for (int k4 = 0; k4 < 16; k4++) {
        float4 xk = x4[k4];
        const float* base = Ws + k4 * 256;
        #pragma unroll
        for (int h4 = 0; h4 < 16; h4++) {
            float4 w0 = ((const float4*)(base      ))[h4];
            float4 w1 = ((const float4*)(base +  64))[h4];
            float4 w2 = ((const float4*)(base + 128))[h4];
            float4 w3 = ((const float4*)(base + 192))[h4];
            float* a = acc + 4 * h4;
            a[0] = fmaf(xk.x, w0.x, fmaf(xk.y, w1.x, fmaf(xk.z, w2.x, fmaf(xk.w, w3.x, a[0]))));
            a[1] = fmaf(xk.x, w0.y, fmaf(xk.y, w1.y, fmaf(xk.z, w2.y, fmaf(xk.w, w3.y, a[1]))));
            a[2] = fmaf(xk.x, w0.z, fmaf(xk.y, w1.z, fmaf(xk.z, w2.z, fmaf(xk.w, w3.z, a[2]))));
            a[3] = fmaf(xk.x, w0.w, fmaf(xk.y, w1.w, fmaf(xk.z, w2.w, fmaf(xk.w, w3.w, a[3]))));
        }
    }
    float4* o4 = (float4*)(g_agg + (size_t)n * 64);
    #pragma unroll
    for (int h4 = 0; h4 < 16; h4++) {
        float4 o;
        o.x = acc[4 * h4 + 0] + bs[4 * h4 + 0];
        o.y = acc[4 * h4 + 1] + bs[4 * h4 + 1];
        o.z = acc[4 * h4 + 2] + bs[4 * h4 + 2];
        o.w = acc[4 * h4 + 3] + bs[4 * h4 + 3];
        o4[h4] = o;
    }
}

// ---------------- BN stats ----------------
__global__ void k_stats() {
    __shared__ float ss[256], sq[256];
    int t = threadIdx.x;                 // 256
    int f = t & 63, g = t >> 6;
    float s = 0.f, q = 0.f;
    for (int n = blockIdx.x * 4 + g; n < NN; n += STATS_BLOCKS * 4) {
        float v = g_agg[n * 64 + f];
        s += v; q = fmaf(v, v, q);
    }
    ss[t] = s; sq[t] = q;
    __syncthreads();
    if (g == 0) {
        s = ss[f] + ss[64 + f] + ss[128 + f] + ss[192 + f];
        q = sq[f] + sq[64 + f] + sq[128 + f] + sq[192 + f];
        g_part[blockIdx.x * 128 + f]      = s;
        g_part[blockIdx.x * 128 + 64 + f] = q;
    }
}

__global__ void k_bnfin(const float* __restrict__ gamma,
                        const float* __restrict__ beta) {
    __shared__ float sh[128];
    int t = threadIdx.x;                 // 128
    float s = 0.f;
    for (int i = 0; i < STATS_BLOCKS; i++) s += g_part[i * 128 + t];
    sh[t] = s;
    __syncthreads();
    if (t < 64) {
        float mean = sh[t] * (1.0f / NN);
        float var  = sh[64 + t] * (1.0f / NN) - mean * mean;
        float sc   = gamma[t] * rsqrtf(var + BN_EPS);
        g_scale[t] = sc;
        g_shift[t] = beta[t] - mean * sc;
    }
}

// ---------------- BN apply + ReLU + residual ----------------
__global__ void k_apply() {
    int id = blockIdx.x * 256 + threadIdx.x;   // over N*16 float4s
    if (id >= NN * 16) return;
    int c = id & 15;
    float4 a = reinterpret_cast<const float4*>(g_agg)[id];
    float4 sc = reinterpret_cast<const float4*>(g_scale)[c];
    float4 sf = reinterpret_cast<const float4*>(g_shift)[c];
    float4 xv = reinterpret_cast<const float4*>(g_x)[id];
    xv.x += fmaxf(fmaf(a.x, sc.x, sf.x), 0.f);
    xv.y += fmaxf(fmaf(a.y, sc.y, sf.y), 0.f);
    xv.z += fmaxf(fmaf(a.z, sc.z, sf.z), 0.f);
    xv.w += fmaxf(fmaf(a.w, sc.w, sf.w), 0.f);
    reinterpret_cast<float4*>(g_x)[id] = xv;
}

// ---------------- edge head ----------------
__global__ void k_final(const int* __restrict__ eio,
                        const float* __restrict__ fcW,   // [128,2]
                        const float* __restrict__ fcb,   // [2]
                        float* __restrict__ out) {
    int wid = (blockIdx.x * 256 + threadIdx.x) >> 5;
    int lane = threadIdx.x & 31;
    if (wid >= EOUT) return;
    int es = eio[wid];
    int ed = eio[EOUT + wid];
    float a0 = 0.f, a1 = 0.f, v;
    v = g_x[es * 64 + lane];
    a0 = fmaf(v, fcW[lane * 2],            a0); a1 = fmaf(v, fcW[lane * 2 + 1],        a1);
    v = g_x[es * 64 + 32 + lane];
    a0 = fmaf(v, fcW[(32 + lane) * 2],     a0); a1 = fmaf(v, fcW[(32 + lane) * 2 + 1], a1);
    v = g_x[ed * 64 + lane];
    a0 = fmaf(v, fcW[(64 + lane) * 2],     a0); a1 = fmaf(v, fcW[(64 + lane) * 2 + 1], a1);
    v = g_x[ed * 64 + 32 + lane];
    a0 = fmaf(v, fcW[(96 + lane) * 2],     a0); a1 = fmaf(v, fcW[(96 + lane) * 2 + 1], a1);
    #pragma unroll
    for (int o = 16; o; o >>= 1) {
        a0 += __shfl_down_sync(0xffffffffu, a0, o);
        a1 += __shfl_down_sync(0xffffffffu, a1, o);
    }
    if (lane == 0) {
        out[wid * 2 + 0] = a0 + fcb[0];
        out[wid * 2 + 1] = a1 + fcb[1];
    }
}

// ---------------- launch ----------------
extern "C" void kernel_launch(void* const* d_in, const int* in_sizes, int n_in,
                              void* d_out, int out_size) {
    const float* x    = (const float*)d_in[0];
    const int*   ei   = (const int*)d_in[1];
    const int*   eio  = (const int*)d_in[2];
    const float* Wemb = (const float*)d_in[3];
    const float* bemb = (const float*)d_in[4];
    const float* convW= (const float*)d_in[5];
    const float* convb= (const float*)d_in[6];
    const float* gam  = (const float*)d_in[7];
    const float* bet  = (const float*)d_in[8];
    const float* fcW  = (const float*)d_in[9];
    const float* fcb  = (const float*)d_in[10];
    float*       out  = (float*)d_out;

    k_deg_init<<<(NN + 255) / 256, 256>>>();
    k_deg_count<<<(EE + 255) / 256, 256>>>(ei);
    k_dinv<<<(NN + 255) / 256, 256>>>();
    k_scan<<<1, 1024>>>();
    k_fill<<<(EE + 255) / 256, 256>>>(ei);
    k_embed<<<(NN * 64 + 255) / 256, 256>>>(x, Wemb, bemb);

    for (int l = 0; l < 6; l++) {
        k_gather<<<(NN * 32 + 255) / 256, 256>>>();
        k_gemm<<<(NN + 255) / 256, 256>>>(convW + l * 64 * 64, convb + l * 64);
        k_stats<<<STATS_BLOCKS, 256>>>();
        k_bnfin<<<1, 128>>>(gam + l * 64, bet + l * 64);
        k_apply<<<(NN * 16 + 255) / 256, 256>>>();
    }

    k_final<<<(EOUT * 32 + 255) / 256, 256>>>(eio, fcW, fcb, out);
}

// round 5
// speedup vs baseline: 2.6580x; 1.1184x over previous
#include <cuda_runtime.h>
#include <cuda_bf16.h>

#define NN   100000
#define EE   1600000
#define EOUT 400000
#define HIDD 64
#define STATS_BLOCKS 128
#define SCAN_BLOCKS  ((NN + 1023) / 1024)
#define BN_EPS 1e-5f

// ---------------- scratch (device globals; no allocation) ----------------
__device__ float g_dinv[NN];
__device__ int   g_deg[NN];
__device__ int   g_rowptr[NN + 1];
__device__ int   g_cursor[NN];
__device__ int   g_bsum[SCAN_BLOCKS];
__device__ int   g_boff[SCAN_BLOCKS];
__device__ int2  g_csr[EE];          // (src, norm-bits)
__device__ float g_x  [NN * HIDD];   // x_embed
__device__ float g_hw [NN * HIDD];   // aggregated x (pre-GEMM)
__device__ float g_agg[NN * HIDD];   // conv output
__device__ float g_part[STATS_BLOCKS * 128];
__device__ float g_scale[HIDD];
__device__ float g_shift[HIDD];
__device__ float4 g_head[NN];        // (a0,a1,b0,b1) edge-head halves

// ---------------- degree ----------------
__global__ void k_deg_init() {
    int i = blockIdx.x * 256 + threadIdx.x;
    if (i < NN) g_deg[i] = 1;            // self loop
}

__global__ void k_deg_count(const int* __restrict__ ei) {
    int e = blockIdx.x * 256 + threadIdx.x;
    if (e < EE) atomicAdd(&g_deg[ei[EE + e]], 1);
}

__global__ void k_dinv() {
    int i = blockIdx.x * 256 + threadIdx.x;
    if (i < NN) g_dinv[i] = rsqrtf((float)g_deg[i]);
}

// ---------------- parallel exclusive scan of (deg-1) ----------------
// phase 1: per-block local exclusive scan + block total
__global__ void k_scan1() {
    __shared__ int wsum[32];
    int tid = threadIdx.x;               // 1024
    int lane = tid & 31, wid = tid >> 5;
    int i = blockIdx.x * 1024 + tid;
    int v = (i < NN) ? g_deg[i] - 1 : 0;
    int incl = v;
    #pragma unroll
    for (int o = 1; o < 32; o <<= 1) {
        int t = __shfl_up_sync(0xffffffffu, incl, o);
        if (lane >= o) incl += t;
    }
    if (lane == 31) wsum[wid] = incl;
    __syncthreads();
    if (wid == 0) {
        int s = wsum[lane];
        #pragma unroll
        for (int o = 1; o < 32; o <<= 1) {
            int t = __shfl_up_sync(0xffffffffu, s, o);
            if (lane >= o) s += t;
        }
        wsum[lane] = s;
    }
    __syncthreads();
    int excl = (wid ? wsum[wid - 1] : 0) + incl - v;
    if (i < NN) g_rowptr[i] = excl;      // block-local offset for now
    if (tid == 1023) g_bsum[blockIdx.x] = wsum[31];   // sole writer (race fixed)
}

// phase 2: serial scan of block sums (tiny)
__global__ void k_scan2() {
    if (threadIdx.x == 0) {
        int run = 0;
        for (int b = 0; b < SCAN_BLOCKS; b++) {
            g_boff[b] = run;
            run += g_bsum[b];
        }
    }
}

// phase 3: add block offsets, init cursor, set rowptr[NN]
__global__ void k_scan3() {
    int i = blockIdx.x * 256 + threadIdx.x;
    if (i < NN) {
        int r = g_rowptr[i] + g_boff[i >> 10];
        g_rowptr[i] = r;
        g_cursor[i] = r;
    }
    if (i == 0) g_rowptr[NN] = EE;       // sum(deg-1) == E exactly
}

// ---------------- CSR fill ----------------
__global__ void k_fill(const int* __restrict__ ei) {
    int e = blockIdx.x * 256 + threadIdx.x;
    if (e >= EE) return;
    int s = ei[e], d = ei[EE + e];
    int p = atomicAdd(&g_cursor[d], 1);
    g_csr[p] = make_int2(s, __float_as_int(g_dinv[s] * g_dinv[d]));
}

// ---------------- node embedding: node per thread, 64 accs ----------------
__global__ void __launch_bounds__(256) k_embed(const float* __restrict__ x,
                                               const float* __restrict__ W,
                                               const float* __restrict__ b) {
    __shared__ float Ws[16 * 64];
    __shared__ float bs[64];
    int tid = threadIdx.x;               // 256
    for (int i = tid; i < 16 * 64; i += 256) Ws[i] = W[i];
    if (tid < 64) bs[tid] = b[tid];
    __syncthreads();
    int n = blockIdx.x * 256 + tid;
    if (n >= NN) return;
    float acc[64];
    #pragma unroll
    for (int h = 0; h < 64; h++) acc[h] = bs[h];
    const float4* x4 = (const float4*)(x + (size_t)n * 16);
    #pragma unroll
    for (int k4 = 0; k4 < 4; k4++) {
        float4 xv = x4[k4];
        #pragma unroll
        for (int kk = 0; kk < 4; kk++) {
            float xk = (&xv.x)[kk];
            const float4* wrow = (const float4*)(Ws + (k4 * 4 + kk) * 64);
            #pragma unroll
            for (int h4 = 0; h4 < 16; h4++) {
                float4 w = wrow[h4];
                float* a = acc + 4 * h4;
                a[0] = fmaf(xk, w.x, a[0]);
                a[1] = fmaf(xk, w.y, a[1]);
                a[2] = fmaf(xk, w.z, a[2]);
                a[3] = fmaf(xk, w.w, a[3]);
            }
        }
    }
    float4* o4 = (float4*)(g_x + (size_t)n * 64);
    #pragma unroll
    for (int h4 = 0; h4 < 16; h4++)
        o4[h4] = make_float4(acc[4*h4], acc[4*h4+1], acc[4*h4+2], acc[4*h4+3]);
}

// ---------------- gather: hw[n] = sum nrm*x[src] + dinv^2*x[n] --------------
__global__ void k_gather() {
    int t = blockIdx.x * 256 + threadIdx.x;
    int node = t >> 5;
    if (node >= NN) return;
    int lane = t & 31;
    const float2* x2 = (const float2*)g_x;
    int beg = g_rowptr[node], end = g_rowptr[node + 1];
    float di = g_dinv[node];
    float2 acc = x2[node * 32 + lane];
    acc.x *= di * di; acc.y *= di * di;
    float2 acc2 = make_float2(0.f, 0.f);
    int i = beg;
    for (; i + 1 < end; i += 2) {
        int2 a = g_csr[i];
        int2 c = g_csr[i + 1];
        float2 va = x2[a.x * 32 + lane];
        float2 vb = x2[c.x * 32 + lane];
        float na = __int_as_float(a.y), nb = __int_as_float(c.y);
        acc.x  = fmaf(na, va.x, acc.x);  acc.y  = fmaf(na, va.y, acc.y);
        acc2.x = fmaf(nb, vb.x, acc2.x); acc2.y = fmaf(nb, vb.y, acc2.y);
    }
    if (i < end) {
        int2 a = g_csr[i];
        float2 va = x2[a.x * 32 + lane];
        float na = __int_as_float(a.y);
        acc.x = fmaf(na, va.x, acc.x); acc.y = fmaf(na, va.y, acc.y);
    }
    acc.x += acc2.x; acc.y += acc2.y;
    ((float2*)g_hw)[node * 32 + lane] = acc;
}

// ---------------- GEMM: agg = hw @ W + b (node per thread) ------------------
__global__ void __launch_bounds__(256) k_gemm(const float* __restrict__ W,
                                              const float* __restrict__ b) {
    __shared__ float Ws[64 * 64];
    __shared__ float bs[64];
    int tid = threadIdx.x;               // 256
    for (int i = tid; i < 64 * 64; i += 256) Ws[i] = W[i];
    if (tid < 64) bs[tid] = b[tid];
    __syncthreads();
    int n = blockIdx.x * 256 + tid;
    if (n >= NN) return;
    float acc[64];
    #pragma unroll
    for (int h = 0; h < 64; h++) acc[h] = 0.f;
    const float4* x4 = (const float4*)(g_hw + (size_t)n * 64);
    for (int k4 = 0; k4 < 16; k4++) {
        float4 xk = x4[k4];
        const float* base = Ws + k4 * 256;
        #pragma unroll
        for (int h4 = 0; h4 < 16; h4++) {
            float4 w0 = ((const float4*)(base      ))[h4];
            float4 w1 = ((const float4*)(base +  64))[h4];
            float4 w2 = ((const float4*)(base + 128))[h4];
            float4 w3 = ((const float4*)(base + 192))[h4];
            float* a = acc + 4 * h4;
            a[0] = fmaf(xk.x, w0.x, fmaf(xk.y, w1.x, fmaf(xk.z, w2.x, fmaf(xk.w, w3.x, a[0]))));
            a[1] = fmaf(xk.x, w0.y, fmaf(xk.y, w1.y, fmaf(xk.z, w2.y, fmaf(xk.w, w3.y, a[1]))));
            a[2] = fmaf(xk.x, w0.z, fmaf(xk.y, w1.z, fmaf(xk.z, w2.z, fmaf(xk.w, w3.z, a[2]))));
            a[3] = fmaf(xk.x, w0.w, fmaf(xk.y, w1.w, fmaf(xk.z, w2.w, fmaf(xk.w, w3.w, a[3]))));
        }
    }
    float4* o4 = (float4*)(g_agg + (size_t)n * 64);
    #pragma unroll
    for (int h4 = 0; h4 < 16; h4++) {
        float4 o;
        o.x = acc[4 * h4 + 0] + bs[4 * h4 + 0];
        o.y = acc[4 * h4 + 1] + bs[4 * h4 + 1];
        o.z = acc[4 * h4 + 2] + bs[4 * h4 + 2];
        o.w = acc[4 * h4 + 3] + bs[4 * h4 + 3];
        o4[h4] = o;
    }
}

// ---------------- BN stats ----------------
__global__ void k_stats() {
    __shared__ float ss[256], sq[256];
    int t = threadIdx.x;                 // 256
    int f = t & 63, g = t >> 6;
    float s = 0.f, q = 0.f;
    for (int n = blockIdx.x * 4 + g; n < NN; n += STATS_BLOCKS * 4) {
        float v = g_agg[n * 64 + f];
        s += v; q = fmaf(v, v, q);
    }
    ss[t] = s; sq[t] = q;
    __syncthreads();
    if (g == 0) {
        s = ss[f] + ss[64 + f] + ss[128 + f] + ss[192 + f];
        q = sq[f] + sq[64 + f] + sq[128 + f] + sq[192 + f];
        g_part[blockIdx.x * 128 + f]      = s;
        g_part[blockIdx.x * 128 + 64 + f] = q;
    }
}

__global__ void k_bnfin(const float* __restrict__ gamma,
                        const float* __restrict__ beta) {
    __shared__ float sh[128];
    int t = threadIdx.x;                 // 128
    float s = 0.f;
    #pragma unroll 4
    for (int i = 0; i < STATS_BLOCKS; i++) s += g_part[i * 128 + t];
    sh[t] = s;
    __syncthreads();
    if (t < 64) {
        float mean = sh[t] * (1.0f / NN);
        float var  = sh[64 + t] * (1.0f / NN) - mean * mean;
        float sc   = gamma[t] * rsqrtf(var + BN_EPS);
        g_scale[t] = sc;
        g_shift[t] = beta[t] - mean * sc;
    }
}

// ---------------- BN apply + ReLU + residual ----------------
__global__ void k_apply() {
    int id = blockIdx.x * 256 + threadIdx.x;   // over N*16 float4s
    if (id >= NN * 16) return;
    int c = id & 15;
    float4 a = reinterpret_cast<const float4*>(g_agg)[id];
    float4 sc = reinterpret_cast<const float4*>(g_scale)[c];
    float4 sf = reinterpret_cast<const float4*>(g_shift)[c];
    float4 xv = reinterpret_cast<const float4*>(g_x)[id];
    xv.x += fmaxf(fmaf(a.x, sc.x, sf.x), 0.f);
    xv.y += fmaxf(fmaf(a.y, sc.y, sf.y), 0.f);
    xv.z += fmaxf(fmaf(a.z, sc.z, sf.z), 0.f);
    xv.w += fmaxf(fmaf(a.w, sc.w, sf.w), 0.f);
    reinterpret_cast<float4*>(g_x)[id] = xv;
}

// ---------------- edge head precompute: head[n] = (x·W0 | x·W1) -------------
__global__ void __launch_bounds__(256) k_headpre(const float* __restrict__ fcW) {
    __shared__ float Ws[128 * 2];
    int tid = threadIdx.x;
    if (tid < 128 * 2) Ws[tid] = fcW[tid];
    __syncthreads();
    int n = blockIdx.x * 256 + tid;
    if (n >= NN) return;
    const float4* x4 = (const float4*)(g_x + (size_t)n * 64);
    float a0 = 0.f, a1 = 0.f, b0 = 0.f, b1 = 0.f;
    #pragma unroll
    for (int k4 = 0; k4 < 16; k4++) {
        float4 xv = x4[k4];
        #pragma unroll
        for (int kk = 0; kk < 4; kk++) {
            float xk = (&xv.x)[kk];
            int h = k4 * 4 + kk;
            a0 = fmaf(xk, Ws[h * 2],            a0);
            a1 = fmaf(xk, Ws[h * 2 + 1],        a1);
            b0 = fmaf(xk, Ws[(64 + h) * 2],     b0);
            b1 = fmaf(xk, Ws[(64 + h) * 2 + 1], b1);
        }
    }
    g_head[n] = make_float4(a0, a1, b0, b1);
}

// ---------------- edge head: out[e] = a[src] + b[dst] + fcb -----------------
__global__ void k_final(const int* __restrict__ eio,
                        const float* __restrict__ fcb,
                        float* __restrict__ out) {
    int e = blockIdx.x * 256 + threadIdx.x;
    if (e >= EOUT) return;
    int s = eio[e];
    int d = eio[EOUT + e];
    float4 hs = g_head[s];
    float4 hd = g_head[d];
    float2 o;
    o.x = hs.x + hd.z + fcb[0];
    o.y = hs.y + hd.w + fcb[1];
    ((float2*)out)[e] = o;
}

// ---------------- launch ----------------
extern "C" void kernel_launch(void* const* d_in, const int* in_sizes, int n_in,
                              void* d_out, int out_size) {
    const float* x    = (const float*)d_in[0];
    const int*   ei   = (const int*)d_in[1];
    const int*   eio  = (const int*)d_in[2];
    const float* Wemb = (const float*)d_in[3];
    const float* bemb = (const float*)d_in[4];
    const float* convW= (const float*)d_in[5];
    const float* convb= (const float*)d_in[6];
    const float* gam  = (const float*)d_in[7];
    const float* bet  = (const float*)d_in[8];
    const float* fcW  = (const float*)d_in[9];
    const float* fcb  = (const float*)d_in[10];
    float*       out  = (float*)d_out;

    k_deg_init<<<(NN + 255) / 256, 256>>>();
    k_deg_count<<<(EE + 255) / 256, 256>>>(ei);
    k_dinv<<<(NN + 255) / 256, 256>>>();
    k_scan1<<<SCAN_BLOCKS, 1024>>>();
    k_scan2<<<1, 32>>>();
    k_scan3<<<(NN + 255) / 256, 256>>>();
    k_fill<<<(EE + 255) / 256, 256>>>(ei);
    k_embed<<<(NN + 255) / 256, 256>>>(x, Wemb, bemb);

    for (int l = 0; l < 6; l++) {
        k_gather<<<(NN * 32 + 255) / 256, 256>>>();
        k_gemm<<<(NN + 255) / 256, 256>>>(convW + l * 64 * 64, convb + l * 64);
        k_stats<<<STATS_BLOCKS, 256>>>();
        k_bnfin<<<1, 128>>>(gam + l * 64, bet + l * 64);
        k_apply<<<(NN * 16 + 255) / 256, 256>>>();
    }

    k_headpre<<<(NN + 255) / 256, 256>>>(fcW);
    k_final<<<(EOUT + 255) / 256, 256>>>(eio, fcb, out);
}